// round 10
// baseline (speedup 1.0000x reference)
#include <cuda_runtime.h>
#include <cuda_fp16.h>
#include <math.h>
#include <cstdint>

#define N_SRC 32768
#define M_TGT 8192
#define D_DIM 64
#define REG_P 0.01f
#define INV_REG 100.0f
#define LOG2E 1.4426950408889634f
#define LN2 0.6931471805599453f

#define BM 64
#define BN 128
#define NT 256
#define NCPSM 3
#define GRID (148 * NCPSM)      // 444
#define NRB (N_SRC / BM)        // 512 row-blocks
#define NCHUNK 4
#define TPC 16                  // tiles per chunk
#define NJOBS (NRB * NCHUNK)    // 2048
#define NSTAGE 4

// ---------------- scratch ----------------
__device__ float  g_tysq[M_TGT];
__device__ float  g_c2[M_TGT];
__device__ float  g_scalars[4];      // 0: 1/mv, 1: 2*invmv*INV_REG*LOG2E, 2: mean(psi)
__device__ __half g_Xh[N_SRC * D_DIM];
__device__ __half g_Yh[M_TGT * D_DIM];
__device__ float  g_pm[NRB * NCHUNK * 4 * BM];   // [rb][ck][nwarp][row]
__device__ float  g_ps[NRB * NCHUNK * 4 * BM];

// ---------------- helpers ----------------
__device__ __forceinline__ uint32_t smem_u32(const void* p) {
    uint32_t a;
    asm("{ .reg .u64 t; cvta.to.shared.u64 t, %1; cvt.u32.u64 %0, t; }" : "=r"(a) : "l"(p));
    return a;
}
__device__ __forceinline__ uint64_t gmem_u64(const void* p) {
    uint64_t a;
    asm("cvta.to.global.u64 %0, %1;" : "=l"(a) : "l"(p));
    return a;
}
__device__ __forceinline__ float ex2f(float x) {
    float r; asm("ex2.approx.ftz.f32 %0, %1;" : "=f"(r) : "f"(x)); return r;
}
__device__ __forceinline__ float lg2f(float x) {
    float r; asm("lg2.approx.f32 %0, %1;" : "=f"(r) : "f"(x)); return r;
}

#define CP_ASYNC16(s, g) \
    asm volatile("cp.async.cg.shared.global [%0], [%1], 16;" :: "r"(s), "l"(g))
#define CP_COMMIT() asm volatile("cp.async.commit_group;" ::: "memory")
#define CP_WAIT(n)  asm volatile("cp.async.wait_group %0;" :: "n"(n) : "memory")

__device__ __forceinline__ void ldsm4(uint32_t* r, uint32_t addr) {
    asm volatile("ldmatrix.sync.aligned.m8n8.x4.shared.b16 {%0,%1,%2,%3}, [%4];"
                 : "=r"(r[0]), "=r"(r[1]), "=r"(r[2]), "=r"(r[3]) : "r"(addr));
}
__device__ __forceinline__ void mma_f16(float* c, const uint32_t* a,
                                        uint32_t b0, uint32_t b1) {
    asm volatile("mma.sync.aligned.m16n8k16.row.col.f32.f16.f16.f32 "
                 "{%0,%1,%2,%3}, {%4,%5,%6,%7}, {%8,%9}, {%0,%1,%2,%3};"
                 : "+f"(c[0]), "+f"(c[1]), "+f"(c[2]), "+f"(c[3])
                 : "r"(a[0]), "r"(a[1]), "r"(a[2]), "r"(a[3]), "r"(b0), "r"(b1));
}

// smem layout (bytes): Xh 8KB | Yh 4x16KB | cs 4x512B
#define SM_X 0
#define SM_Y 8192
#define SM_C (8192 + NSTAGE * 16384)
#define SM_TOTAL (SM_C + NSTAGE * 512)      // 75776

// ---------------- prologue kernels ----------------
__global__ void convX_kernel(const float* __restrict__ src) {
    int i = blockIdx.x * blockDim.x + threadIdx.x;
    if (i >= N_SRC * D_DIM / 2) return;
    float2 v = reinterpret_cast<const float2*>(src)[i];
    reinterpret_cast<__half2*>(g_Xh)[i] = __float22half2_rn(v);
}

__global__ void convY_tysq_kernel(const float* __restrict__ Y) {
    int gid = blockIdx.x * blockDim.x + threadIdx.x;
    int r = gid >> 3, c8 = gid & 7;
    const float4* p = reinterpret_cast<const float4*>(Y + (size_t)r * D_DIM + c8 * 8);
    float4 v0 = p[0], v1 = p[1];
    __half2 h[4];
    h[0] = __float22half2_rn(make_float2(v0.x, v0.y));
    h[1] = __float22half2_rn(make_float2(v0.z, v0.w));
    h[2] = __float22half2_rn(make_float2(v1.x, v1.y));
    h[3] = __float22half2_rn(make_float2(v1.z, v1.w));
    *reinterpret_cast<uint4*>(g_Yh + (size_t)r * D_DIM + c8 * 8) =
        *reinterpret_cast<uint4*>(h);
    float s = v0.x * v0.x + v0.y * v0.y + v0.z * v0.z + v0.w * v0.w
            + v1.x * v1.x + v1.y * v1.y + v1.z * v1.z + v1.w * v1.w;
    s += __shfl_down_sync(0xffffffffu, s, 4, 8);
    s += __shfl_down_sync(0xffffffffu, s, 2, 8);
    s += __shfl_down_sync(0xffffffffu, s, 1, 8);
    if (c8 == 0) g_tysq[r] = s;
}

__global__ void prep_kernel(const float* __restrict__ psi) {
    __shared__ float red_t[1024];
    __shared__ float red_p[1024];
    __shared__ float inv_mv_s;
    int t = threadIdx.x;
    float st = 0.f, sp = 0.f;
    for (int m = t; m < M_TGT; m += 1024) { st += g_tysq[m]; sp += psi[m]; }
    red_t[t] = st; red_p[t] = sp;
    __syncthreads();
    for (int off = 512; off > 0; off >>= 1) {
        if (t < off) { red_t[t] += red_t[t + off]; red_p[t] += red_p[t + off]; }
        __syncthreads();
    }
    if (t == 0) {
        float mv = red_t[0] / (float)M_TGT;
        float inv_mv = 1.0f / mv;
        g_scalars[0] = inv_mv;
        g_scalars[1] = 2.0f * inv_mv * INV_REG * LOG2E;
        g_scalars[2] = red_p[0] / (float)M_TGT;
        inv_mv_s = inv_mv;
    }
    __syncthreads();
    float inv_mv = inv_mv_s;
    for (int m = t; m < M_TGT; m += 1024)
        g_c2[m] = (psi[m] - g_tysq[m] * inv_mv) * (INV_REG * LOG2E);
}

// ---------------- main kernel: 8 warps/CTA, 3 CTAs/SM, persistent ----------
extern __shared__ char smem[];

__device__ __forceinline__ void prefetch_tile(uint32_t sb, uint64_t Yg, uint64_t Cg,
                                              int gt, int stg, int tid) {
#pragma unroll
    for (int i = 0; i < 4; i++) {
        int idx = tid + i * NT;          // 1024 chunks
        int row = idx >> 3, ch = idx & 7;
        uint32_t s = sb + SM_Y + stg * 16384 + row * 128 + ((ch ^ (row & 7)) << 4);
        uint64_t g = Yg + (uint64_t)(gt * BN + row) * 128 + ch * 16;
        CP_ASYNC16(s, g);
    }
    if (tid < 32) {
        uint32_t s = sb + SM_C + stg * 512 + tid * 16;
        uint64_t g = Cg + (uint64_t)(gt * BN + tid * 4) * 4;
        CP_ASYNC16(s, g);
    }
}

__global__ __launch_bounds__(NT, NCPSM)
void lse_mma_kernel() {
    const uint32_t sb = smem_u32(smem);
    const int tid  = threadIdx.x;
    const int lane = tid & 31;
    const int wid  = tid >> 5;
    const int mwarp = wid & 1;           // rows mwarp*32..+31
    const int nwarp = wid >> 1;          // cols nwarp*32..+31  (0..3)
    const int q  = lane & 3;
    const int g4 = lane >> 2;

    const float s2 = g_scalars[1];

    const uint64_t Yg = gmem_u64(g_Yh);
    const uint64_t Cg = gmem_u64(g_c2);

    const int b = lane >> 3, lr = lane & 7;
    const int rselA = (b & 1) * 8, cselA = b >> 1;
    const int rselB = (b >> 1) * 8, cselB = b & 1;

    for (int job = blockIdx.x; job < NJOBS; job += GRID) {
        const int rb = job >> 2;
        const int ck = job & 3;
        const int rowBase = rb * BM;
        const int tile0 = ck * TPC;

        __syncthreads();   // all warps done with previous job's smem

        // ---- X tile (fp16, 64 rows) -> smem : 512 chunks / 256 threads ----
#pragma unroll
        for (int i = 0; i < 2; i++) {
            int idx = tid + i * NT;
            int row = idx >> 3, ch = idx & 7;
            uint4 v = *reinterpret_cast<const uint4*>(
                reinterpret_cast<const char*>(g_Xh) +
                (uint64_t)(rowBase + row) * 128 + ch * 16);
            *reinterpret_cast<uint4*>(smem + SM_X + row * 128 +
                                      ((ch ^ (row & 7)) << 4)) = v;
        }
        // ---- prefetch tiles 0..2 ----
#pragma unroll
        for (int pt = 0; pt < NSTAGE - 1; pt++) {
            prefetch_tile(sb, Yg, Cg, tile0 + pt, pt, tid);
            CP_COMMIT();
        }
        __syncthreads();   // X visible

        float runm[4], runs[4];   // [mt*2 + rowhalf]
#pragma unroll
        for (int r = 0; r < 4; r++) { runm[r] = -INFINITY; runs[r] = 0.f; }

        for (int t = 0; t < TPC; t++) {
            CP_WAIT(2);
            __syncthreads();
            const int buf = t & (NSTAGE - 1);
            const uint32_t yb = sb + SM_Y + buf * 16384;

            if (t + NSTAGE - 1 < TPC)
                prefetch_tile(sb, Yg, Cg, tile0 + t + NSTAGE - 1,
                              (t + NSTAGE - 1) & (NSTAGE - 1), tid);
            CP_COMMIT();

            // ---- A fragments for this tile (transient): 8 ldsm, 32 regs ----
            uint32_t A[2][4][4];
#pragma unroll
            for (int mt = 0; mt < 2; mt++)
#pragma unroll
                for (int ks = 0; ks < 4; ks++) {
                    int row = mwarp * 32 + mt * 16 + rselA + lr;
                    int ch  = ks * 2 + cselA;
                    ldsm4(A[mt][ks], sb + SM_X + row * 128 + ((ch ^ lr) << 4));
                }

#pragma unroll
            for (int nt2 = 0; nt2 < 2; nt2++) {
                const uint32_t rowb =
                    yb + (uint32_t)(nwarp * 32 + nt2 * 16 + rselB + lr) * 128;
                // c fragments for these 16 cols (4 floats/lane)
                float2 cp0, cp1;
                {
                    const float* cbB =
                        reinterpret_cast<const float*>(smem + SM_C + buf * 512)
                        + nwarp * 32 + nt2 * 16;
                    cp0 = *reinterpret_cast<const float2*>(cbB + q * 2);
                    cp1 = *reinterpret_cast<const float2*>(cbB + 8 + q * 2);
                }
                float acc[2][2][4];
#pragma unroll
                for (int mt = 0; mt < 2; mt++)
#pragma unroll
                    for (int nf = 0; nf < 2; nf++)
#pragma unroll
                        for (int j = 0; j < 4; j++) acc[mt][nf][j] = 0.f;

#pragma unroll
                for (int ks = 0; ks < 4; ks++) {
                    uint32_t B[4];
                    ldsm4(B, rowb + (((ks * 2 + cselB) ^ lr) << 4));
#pragma unroll
                    for (int mt = 0; mt < 2; mt++) {
                        mma_f16(acc[mt][0], A[mt][ks], B[0], B[1]);
                        mma_f16(acc[mt][1], A[mt][ks], B[2], B[3]);
                    }
                }

                // epilogue: one prune region per mt (covers both row-halves)
#pragma unroll
                for (int mt = 0; mt < 2; mt++) {
                    const int r0 = mt * 2, r1 = mt * 2 + 1;
                    float v00 = fmaf(s2, acc[mt][0][0], cp0.x);
                    float v01 = fmaf(s2, acc[mt][0][1], cp0.y);
                    float v02 = fmaf(s2, acc[mt][1][0], cp1.x);
                    float v03 = fmaf(s2, acc[mt][1][1], cp1.y);
                    float v10 = fmaf(s2, acc[mt][0][2], cp0.x);
                    float v11 = fmaf(s2, acc[mt][0][3], cp0.y);
                    float v12 = fmaf(s2, acc[mt][1][2], cp1.x);
                    float v13 = fmaf(s2, acc[mt][1][3], cp1.y);
                    float mx0 = fmaxf(fmaxf(v00, v01), fmaxf(v02, v03));
                    float mx1 = fmaxf(fmaxf(v10, v11), fmaxf(v12, v13));
                    if (fmaxf(mx0, mx1) > fminf(runm[r0], runm[r1]) - 20.f) {
                        float nm0 = fmaxf(runm[r0], mx0);
                        float nm1 = fmaxf(runm[r1], mx1);
                        runs[r0] = runs[r0] * ex2f(runm[r0] - nm0)
                                 + ((ex2f(v00 - nm0) + ex2f(v01 - nm0))
                                  + (ex2f(v02 - nm0) + ex2f(v03 - nm0)));
                        runs[r1] = runs[r1] * ex2f(runm[r1] - nm1)
                                 + ((ex2f(v10 - nm1) + ex2f(v11 - nm1))
                                  + (ex2f(v12 - nm1) + ex2f(v13 - nm1)));
                        runm[r0] = nm0;
                        runm[r1] = nm1;
                    }
                }
            }
        }

        // ---- merge across 4 q-lanes per row; write partials ----
#pragma unroll
        for (int r = 0; r < 4; r++) {
            float m = runm[r], s = runs[r];
#pragma unroll
            for (int off = 1; off < 4; off <<= 1) {
                float m2 = __shfl_xor_sync(0xffffffffu, m, off);
                float s2x = __shfl_xor_sync(0xffffffffu, s, off);
                float nm = fmaxf(m, m2);
                s = s * ex2f(m - nm) + s2x * ex2f(m2 - nm);
                m = nm;
            }
            if (q == 0) {
                int mt = r >> 1, hf = r & 1;
                int rl = mwarp * 32 + mt * 16 + hf * 8 + g4;
                int idx = ((rb * NCHUNK + ck) * 4 + nwarp) * BM + rl;
                g_pm[idx] = m;
                g_ps[idx] = s;
            }
        }
    }
}

// ---------------- finalize: merge 16 partials/row ----------------
__global__ void final_kernel(const float* __restrict__ X, float* __restrict__ out) {
    int r = blockIdx.x * blockDim.x + threadIdx.x;
    if (r >= N_SRC) return;
    int rb = r >> 6, rl = r & 63;
    const float invmv = g_scalars[0];
    const float mpsi  = g_scalars[2];
    float m = -INFINITY, s = 0.f;
#pragma unroll
    for (int ck = 0; ck < NCHUNK; ck++)
#pragma unroll
        for (int nw = 0; nw < 4; nw++) {
            int idx = ((rb * NCHUNK + ck) * 4 + nw) * BM + rl;
            float m2 = g_pm[idx], s2v = g_ps[idx];
            float nm = fmaxf(m, m2);
            s = s * ex2f(m - nm) + s2v * ex2f(m2 - nm);
            m = nm;
        }
    const float4* xr = reinterpret_cast<const float4*>(X + (size_t)r * D_DIM);
    float xs = 0.f;
#pragma unroll
    for (int i = 0; i < 16; i++) {
        float4 v = xr[i];
        xs = fmaf(v.x, v.x, fmaf(v.y, v.y, fmaf(v.z, v.z, fmaf(v.w, v.w, xs))));
    }
    out[r] = fmaf(xs, invmv, mpsi) - (REG_P * LN2) * (m + lg2f(s));
}

// ---------------- launch ----------------
extern "C" void kernel_launch(void* const* d_in, const int* in_sizes, int n_in,
                              void* d_out, int out_size) {
    const float *X = nullptr, *Y = nullptr, *psi = nullptr;
    for (int i = 0; i < n_in; i++) {
        if (in_sizes[i] == N_SRC * D_DIM)      X   = (const float*)d_in[i];
        else if (in_sizes[i] == M_TGT * D_DIM) Y   = (const float*)d_in[i];
        else if (in_sizes[i] == M_TGT)         psi = (const float*)d_in[i];
    }
    float* out = (float*)d_out;

    convX_kernel<<<(N_SRC * D_DIM / 2 + 255) / 256, 256>>>(X);
    convY_tysq_kernel<<<(M_TGT * 8) / 256, 256>>>(Y);
    prep_kernel<<<1, 1024>>>(psi);

    cudaFuncSetAttribute(lse_mma_kernel,
                         cudaFuncAttributeMaxDynamicSharedMemorySize, SM_TOTAL);
    lse_mma_kernel<<<GRID, NT, SM_TOTAL>>>();

    final_kernel<<<N_SRC / 256, 256>>>(X, out);
}

// round 11
// speedup vs baseline: 1.2514x; 1.2514x over previous
#include <cuda_runtime.h>
#include <cuda_fp16.h>
#include <math.h>
#include <cstdint>

#define N_SRC 32768
#define M_TGT 8192
#define D_DIM 64
#define REG_P 0.01f
#define INV_REG 100.0f
#define LOG2E 1.4426950408889634f
#define LN2 0.6931471805599453f

#define BM 128
#define BN 64
#define NT 256
#define NCPSM 3
#define GRID (148 * NCPSM)      // 444
#define NRB (N_SRC / BM)        // 256 row-blocks
#define NCHUNK 8
#define TPC 16                  // 64-row tiles per chunk (8192/64/8)
#define NJOBS (NRB * NCHUNK)    // 2048
#define NSTAGE 4

// ---------------- scratch ----------------
__device__ float  g_tysq[M_TGT];
__device__ float  g_c2[M_TGT];
__device__ float  g_scalars[4];      // 0: 1/mv, 1: 2*invmv*INV_REG*LOG2E, 2: mean(psi)
__device__ __half g_Xh[N_SRC * D_DIM];
__device__ __half g_Yh[M_TGT * D_DIM];
__device__ float  g_pm[NRB * NCHUNK * 2 * BM];   // [rb][ck][nwarp][row]
__device__ float  g_ps[NRB * NCHUNK * 2 * BM];
__device__ int    g_job;

// ---------------- helpers ----------------
__device__ __forceinline__ uint32_t smem_u32(const void* p) {
    uint32_t a;
    asm("{ .reg .u64 t; cvta.to.shared.u64 t, %1; cvt.u32.u64 %0, t; }" : "=r"(a) : "l"(p));
    return a;
}
__device__ __forceinline__ uint64_t gmem_u64(const void* p) {
    uint64_t a;
    asm("cvta.to.global.u64 %0, %1;" : "=l"(a) : "l"(p));
    return a;
}
__device__ __forceinline__ float ex2f(float x) {
    float r; asm("ex2.approx.ftz.f32 %0, %1;" : "=f"(r) : "f"(x)); return r;
}
__device__ __forceinline__ float lg2f(float x) {
    float r; asm("lg2.approx.f32 %0, %1;" : "=f"(r) : "f"(x)); return r;
}

#define CP_ASYNC16(s, g) \
    asm volatile("cp.async.cg.shared.global [%0], [%1], 16;" :: "r"(s), "l"(g))
#define CP_COMMIT() asm volatile("cp.async.commit_group;" ::: "memory")
#define CP_WAIT(n)  asm volatile("cp.async.wait_group %0;" :: "n"(n) : "memory")

__device__ __forceinline__ void ldsm4(uint32_t* r, uint32_t addr) {
    asm volatile("ldmatrix.sync.aligned.m8n8.x4.shared.b16 {%0,%1,%2,%3}, [%4];"
                 : "=r"(r[0]), "=r"(r[1]), "=r"(r[2]), "=r"(r[3]) : "r"(addr));
}
__device__ __forceinline__ void mma_f16(float* c, const uint32_t* a,
                                        uint32_t b0, uint32_t b1) {
    asm volatile("mma.sync.aligned.m16n8k16.row.col.f32.f16.f16.f32 "
                 "{%0,%1,%2,%3}, {%4,%5,%6,%7}, {%8,%9}, {%0,%1,%2,%3};"
                 : "+f"(c[0]), "+f"(c[1]), "+f"(c[2]), "+f"(c[3])
                 : "r"(a[0]), "r"(a[1]), "r"(a[2]), "r"(a[3]), "r"(b0), "r"(b1));
}

// smem layout (bytes): Xh 16KB | Yh 4x8KB | cs 4x256B
#define SM_X 0
#define SM_Y 16384
#define SM_C (16384 + NSTAGE * 8192)
#define SM_TOTAL (SM_C + NSTAGE * 256 + 128)   // ~50.4 KB; x3 CTAs fits

// ---------------- prologue kernels ----------------
__global__ void convX_kernel(const float* __restrict__ src) {
    int i = blockIdx.x * blockDim.x + threadIdx.x;
    if (i >= N_SRC * D_DIM / 2) return;
    float2 v = reinterpret_cast<const float2*>(src)[i];
    reinterpret_cast<__half2*>(g_Xh)[i] = __float22half2_rn(v);
}

__global__ void convY_tysq_kernel(const float* __restrict__ Y) {
    int gid = blockIdx.x * blockDim.x + threadIdx.x;
    int r = gid >> 3, c8 = gid & 7;
    const float4* p = reinterpret_cast<const float4*>(Y + (size_t)r * D_DIM + c8 * 8);
    float4 v0 = p[0], v1 = p[1];
    __half2 h[4];
    h[0] = __float22half2_rn(make_float2(v0.x, v0.y));
    h[1] = __float22half2_rn(make_float2(v0.z, v0.w));
    h[2] = __float22half2_rn(make_float2(v1.x, v1.y));
    h[3] = __float22half2_rn(make_float2(v1.z, v1.w));
    *reinterpret_cast<uint4*>(g_Yh + (size_t)r * D_DIM + c8 * 8) =
        *reinterpret_cast<uint4*>(h);
    float s = v0.x * v0.x + v0.y * v0.y + v0.z * v0.z + v0.w * v0.w
            + v1.x * v1.x + v1.y * v1.y + v1.z * v1.z + v1.w * v1.w;
    s += __shfl_down_sync(0xffffffffu, s, 4, 8);
    s += __shfl_down_sync(0xffffffffu, s, 2, 8);
    s += __shfl_down_sync(0xffffffffu, s, 1, 8);
    if (c8 == 0) g_tysq[r] = s;
}

__global__ void prep_kernel(const float* __restrict__ psi) {
    __shared__ float red_t[1024];
    __shared__ float red_p[1024];
    __shared__ float inv_mv_s;
    int t = threadIdx.x;
    float st = 0.f, sp = 0.f;
    for (int m = t; m < M_TGT; m += 1024) { st += g_tysq[m]; sp += psi[m]; }
    red_t[t] = st; red_p[t] = sp;
    __syncthreads();
    for (int off = 512; off > 0; off >>= 1) {
        if (t < off) { red_t[t] += red_t[t + off]; red_p[t] += red_p[t + off]; }
        __syncthreads();
    }
    if (t == 0) {
        float mv = red_t[0] / (float)M_TGT;
        float inv_mv = 1.0f / mv;
        g_scalars[0] = inv_mv;
        g_scalars[1] = 2.0f * inv_mv * INV_REG * LOG2E;
        g_scalars[2] = red_p[0] / (float)M_TGT;
        inv_mv_s = inv_mv;
        g_job = GRID;                       // reset work-steal counter
    }
    __syncthreads();
    float inv_mv = inv_mv_s;
    for (int m = t; m < M_TGT; m += 1024)
        g_c2[m] = (psi[m] - g_tysq[m] * inv_mv) * (INV_REG * LOG2E);
}

// ---------------- main kernel ----------------
extern __shared__ char smem[];

__device__ __forceinline__ void prefetch_tile(uint32_t sb, uint64_t Yg, uint64_t Cg,
                                              int gt, int stg, int tid) {
    // Y tile: 64 rows x 128B = 512 chunks of 16B
#pragma unroll
    for (int i = 0; i < 2; i++) {
        int idx = tid + i * NT;
        int row = idx >> 3, ch = idx & 7;
        uint32_t s = sb + SM_Y + stg * 8192 + row * 128 + ((ch ^ (row & 7)) << 4);
        uint64_t g = Yg + (uint64_t)(gt * BN + row) * 128 + ch * 16;
        CP_ASYNC16(s, g);
    }
    if (tid < 16) {
        uint32_t s = sb + SM_C + stg * 256 + tid * 16;
        uint64_t g = Cg + (uint64_t)(gt * BN + tid * 4) * 4;
        CP_ASYNC16(s, g);
    }
}

__global__ __launch_bounds__(NT, NCPSM)
void lse_mma_kernel() {
    __shared__ int job_s;
    const uint32_t sb = smem_u32(smem);
    const int tid  = threadIdx.x;
    const int lane = tid & 31;
    const int wid  = tid >> 5;
    const int mwarp = wid >> 1;          // 0..3 -> rows mwarp*32..+31
    const int nwarp = wid & 1;           // 0..1 -> cols nwarp*32..+31
    const int q  = lane & 3;
    const int g4 = lane >> 2;

    const float s2 = g_scalars[1];

    const uint64_t Yg = gmem_u64(g_Yh);
    const uint64_t Cg = gmem_u64(g_c2);

    const int b = lane >> 3, lr = lane & 7;
    const int rselA = (b & 1) * 8, cselA = b >> 1;
    const int rselB = (b >> 1) * 8, cselB = b & 1;

    int job = blockIdx.x;
    while (job < NJOBS) {
        const int rb = job >> 3;
        const int ck = job & 7;
        const int rowBase = rb * BM;
        const int tile0 = ck * TPC;      // in units of 64-row tiles

        // ---- X tile (fp16, 128 rows) -> smem : 1024 chunks ----
#pragma unroll
        for (int i = 0; i < 4; i++) {
            int idx = tid + i * NT;
            int row = idx >> 3, ch = idx & 7;
            uint4 v = *reinterpret_cast<const uint4*>(
                reinterpret_cast<const char*>(g_Xh) +
                (uint64_t)(rowBase + row) * 128 + ch * 16);
            *reinterpret_cast<uint4*>(smem + SM_X + row * 128 +
                                      ((ch ^ (row & 7)) << 4)) = v;
        }
        // ---- prefetch Y tiles 0..2 ----
#pragma unroll
        for (int pt = 0; pt < NSTAGE - 1; pt++) {
            prefetch_tile(sb, Yg, Cg, tile0 + pt, pt, tid);
            CP_COMMIT();
        }
        __syncthreads();   // X visible

        // ---- A fragments (persistent for the job): 32 regs ----
        uint32_t A[2][4][4];
#pragma unroll
        for (int mt = 0; mt < 2; mt++)
#pragma unroll
            for (int ks = 0; ks < 4; ks++) {
                int row = mwarp * 32 + mt * 16 + rselA + lr;
                int ch  = ks * 2 + cselA;
                ldsm4(A[mt][ks], sb + SM_X + row * 128 + ((ch ^ lr) << 4));
            }

        float runm[4], runs[4];   // [mt*2 + rowhalf]
#pragma unroll
        for (int r = 0; r < 4; r++) { runm[r] = -INFINITY; runs[r] = 0.f; }

        for (int t = 0; t < TPC; t++) {
            CP_WAIT(2);
            __syncthreads();
            const int buf = t & (NSTAGE - 1);
            const uint32_t yb = sb + SM_Y + buf * 8192;

            if (t + NSTAGE - 1 < TPC)
                prefetch_tile(sb, Yg, Cg, tile0 + t + NSTAGE - 1,
                              (t + NSTAGE - 1) & (NSTAGE - 1), tid);
            CP_COMMIT();

#pragma unroll
            for (int nt2 = 0; nt2 < 2; nt2++) {
                const uint32_t rowb =
                    yb + (uint32_t)(nwarp * 32 + nt2 * 16 + rselB + lr) * 128;
                float2 cp0, cp1;
                {
                    const float* cbB =
                        reinterpret_cast<const float*>(smem + SM_C + buf * 256)
                        + nwarp * 32 + nt2 * 16;
                    cp0 = *reinterpret_cast<const float2*>(cbB + q * 2);
                    cp1 = *reinterpret_cast<const float2*>(cbB + 8 + q * 2);
                }
                float acc[2][2][4];
#pragma unroll
                for (int mt = 0; mt < 2; mt++)
#pragma unroll
                    for (int nf = 0; nf < 2; nf++)
#pragma unroll
                        for (int j = 0; j < 4; j++) acc[mt][nf][j] = 0.f;

#pragma unroll
                for (int ks = 0; ks < 4; ks++) {
                    uint32_t B[4];
                    ldsm4(B, rowb + (((ks * 2 + cselB) ^ lr) << 4));
#pragma unroll
                    for (int mt = 0; mt < 2; mt++) {
                        mma_f16(acc[mt][0], A[mt][ks], B[0], B[1]);
                        mma_f16(acc[mt][1], A[mt][ks], B[2], B[3]);
                    }
                }

                // epilogue: one prune region per mt (covers both row-halves)
#pragma unroll
                for (int mt = 0; mt < 2; mt++) {
                    const int r0 = mt * 2, r1 = mt * 2 + 1;
                    float v00 = fmaf(s2, acc[mt][0][0], cp0.x);
                    float v01 = fmaf(s2, acc[mt][0][1], cp0.y);
                    float v02 = fmaf(s2, acc[mt][1][0], cp1.x);
                    float v03 = fmaf(s2, acc[mt][1][1], cp1.y);
                    float v10 = fmaf(s2, acc[mt][0][2], cp0.x);
                    float v11 = fmaf(s2, acc[mt][0][3], cp0.y);
                    float v12 = fmaf(s2, acc[mt][1][2], cp1.x);
                    float v13 = fmaf(s2, acc[mt][1][3], cp1.y);
                    float mx0 = fmaxf(fmaxf(v00, v01), fmaxf(v02, v03));
                    float mx1 = fmaxf(fmaxf(v10, v11), fmaxf(v12, v13));
                    if (fmaxf(mx0, mx1) > fminf(runm[r0], runm[r1]) - 20.f) {
                        float nm0 = fmaxf(runm[r0], mx0);
                        float nm1 = fmaxf(runm[r1], mx1);
                        runs[r0] = runs[r0] * ex2f(runm[r0] - nm0)
                                 + ((ex2f(v00 - nm0) + ex2f(v01 - nm0))
                                  + (ex2f(v02 - nm0) + ex2f(v03 - nm0)));
                        runs[r1] = runs[r1] * ex2f(runm[r1] - nm1)
                                 + ((ex2f(v10 - nm1) + ex2f(v11 - nm1))
                                  + (ex2f(v12 - nm1) + ex2f(v13 - nm1)));
                        runm[r0] = nm0;
                        runm[r1] = nm1;
                    }
                }
            }
        }

        // ---- merge across 4 q-lanes per row; write partials ----
#pragma unroll
        for (int r = 0; r < 4; r++) {
            float m = runm[r], s = runs[r];
#pragma unroll
            for (int off = 1; off < 4; off <<= 1) {
                float m2 = __shfl_xor_sync(0xffffffffu, m, off);
                float s2x = __shfl_xor_sync(0xffffffffu, s, off);
                float nm = fmaxf(m, m2);
                s = s * ex2f(m - nm) + s2x * ex2f(m2 - nm);
                m = nm;
            }
            if (q == 0) {
                int mt = r >> 1, hf = r & 1;
                int rl = mwarp * 32 + mt * 16 + hf * 8 + g4;
                int idx = ((rb * NCHUNK + ck) * 2 + nwarp) * BM + rl;
                g_pm[idx] = m;
                g_ps[idx] = s;
            }
        }

        // ---- steal next job (doubles as end-of-job barrier) ----
        if (tid == 0) job_s = atomicAdd(&g_job, 1);
        __syncthreads();
        job = job_s;
    }
}

// ---------------- finalize: merge 16 partials/row ----------------
__global__ void final_kernel(const float* __restrict__ X, float* __restrict__ out) {
    int r = blockIdx.x * blockDim.x + threadIdx.x;
    if (r >= N_SRC) return;
    int rb = r >> 7, rl = r & 127;
    const float invmv = g_scalars[0];
    const float mpsi  = g_scalars[2];
    float m = -INFINITY, s = 0.f;
#pragma unroll
    for (int ck = 0; ck < NCHUNK; ck++)
#pragma unroll
        for (int nw = 0; nw < 2; nw++) {
            int idx = ((rb * NCHUNK + ck) * 2 + nw) * BM + rl;
            float m2 = g_pm[idx], s2v = g_ps[idx];
            float nm = fmaxf(m, m2);
            s = s * ex2f(m - nm) + s2v * ex2f(m2 - nm);
            m = nm;
        }
    const float4* xr = reinterpret_cast<const float4*>(X + (size_t)r * D_DIM);
    float xs = 0.f;
#pragma unroll
    for (int i = 0; i < 16; i++) {
        float4 v = xr[i];
        xs = fmaf(v.x, v.x, fmaf(v.y, v.y, fmaf(v.z, v.z, fmaf(v.w, v.w, xs))));
    }
    out[r] = fmaf(xs, invmv, mpsi) - (REG_P * LN2) * (m + lg2f(s));
}

// ---------------- launch ----------------
extern "C" void kernel_launch(void* const* d_in, const int* in_sizes, int n_in,
                              void* d_out, int out_size) {
    const float *X = nullptr, *Y = nullptr, *psi = nullptr;
    for (int i = 0; i < n_in; i++) {
        if (in_sizes[i] == N_SRC * D_DIM)      X   = (const float*)d_in[i];
        else if (in_sizes[i] == M_TGT * D_DIM) Y   = (const float*)d_in[i];
        else if (in_sizes[i] == M_TGT)         psi = (const float*)d_in[i];
    }
    float* out = (float*)d_out;

    convX_kernel<<<(N_SRC * D_DIM / 2 + 255) / 256, 256>>>(X);
    convY_tysq_kernel<<<(M_TGT * 8) / 256, 256>>>(Y);
    prep_kernel<<<1, 1024>>>(psi);

    cudaFuncSetAttribute(lse_mma_kernel,
                         cudaFuncAttributeMaxDynamicSharedMemorySize, SM_TOTAL);
    lse_mma_kernel<<<GRID, NT, SM_TOTAL>>>();

    final_kernel<<<N_SRC / 256, 256>>>(X, out);
}